// round 15
// baseline (speedup 1.0000x reference)
#include <cuda_runtime.h>
#include <cuda_fp16.h>
#include <cstdint>

// Batched NT GEMM, fp16 tensor cores (fp32 acc), pre-converted f16 operands:
//   C[b,i,j] = sum_d A[b,i,d] * B[b,j,d]
// A,B: [16,1024,256] f32 row-major, C: [16,1024,1024] f32.
//
// Pass 1: A,B f32 -> f16 (RTN) into __device__ scratch (~6us).
// Pass 2: persistent mbarrier-ring GEMM, CTA 128x128, warp 64x32, 8 warps,
// 2 CTAs/SM, grid 304, BK=64 (f16 row = 128B line, SW128 swizzle u^(row&7)),
// 3 stages. R15 fix vs R14: B ldmatrix n-group stride is 16 rows = 2048B in
// the 1-row-per-line layout (R14 kept R13's 1024B from the 2-rows-per-line
// layout, corrupting n 8..31 of every warp tile -> rel_err ~1).
// fp32 accumulate; cvt.rn unbiased => no correction factor.

#define BATCH 16
#define RDIM  1024
#define DDIM  256

#define BM 128
#define BN 128
#define BK 64
#define STAGES 3
#define KTILES (DDIM / BK)   // 4
#define NTHREADS 256
#define NTILES  (BATCH * (RDIM / BM) * (RDIM / BN))   // 1024
#define GRIDC   304

#define STAGE_BYTES 16384                      // 128 rows x 128B (f16), per operand
#define B_BASE      (STAGES * STAGE_BYTES)     // 49152
#define MB_OFF      (2 * STAGES * STAGE_BYTES) // 98304
#define SMEM_TOTAL  (MB_OFF + 64)

// f16 scratch (static device arrays: the sanctioned no-alloc workaround)
__device__ __align__(16) __half g_Ah[BATCH * RDIM * DDIM];   // 8.4 MB
__device__ __align__(16) __half g_Bh[BATCH * RDIM * DDIM];   // 8.4 MB

__device__ __forceinline__ uint32_t smem_u32(const void* p) {
    uint32_t a;
    asm("{ .reg .u64 t; cvta.to.shared.u64 t, %1; cvt.u32.u64 %0, t; }" : "=r"(a) : "l"(p));
    return a;
}

__device__ __forceinline__ void cp_async16(uint32_t dst, const void* src) {
    asm volatile("cp.async.cg.shared.global [%0], [%1], 16;" :: "r"(dst), "l"(src) : "memory");
}

__device__ __forceinline__ void mbar_init(uint32_t mbar, uint32_t count) {
    asm volatile("mbarrier.init.shared.b64 [%0], %1;" :: "r"(mbar), "r"(count) : "memory");
}
__device__ __forceinline__ void mbar_arrive(uint32_t mbar) {
    asm volatile("mbarrier.arrive.shared.b64 _, [%0];" :: "r"(mbar) : "memory");
}
__device__ __forceinline__ void cp_arrive_noinc(uint32_t mbar) {
    asm volatile("cp.async.mbarrier.arrive.noinc.shared.b64 [%0];" :: "r"(mbar) : "memory");
}
__device__ __forceinline__ void mbar_wait(uint32_t mbar, uint32_t parity) {
    asm volatile(
        "{\n\t"
        ".reg .pred P;\n\t"
        "WAIT_%=:\n\t"
        "mbarrier.try_wait.parity.acquire.cta.shared::cta.b64 P, [%0], %1, 0x989680;\n\t"
        "@P bra DONE_%=;\n\t"
        "bra WAIT_%=;\n\t"
        "DONE_%=:\n\t"
        "}"
        :: "r"(mbar), "r"(parity) : "memory");
}

__device__ __forceinline__ void ldsm4(uint32_t* d, uint32_t addr) {
    asm volatile("ldmatrix.sync.aligned.m8n8.x4.shared.b16 {%0,%1,%2,%3}, [%4];"
                 : "=r"(d[0]), "=r"(d[1]), "=r"(d[2]), "=r"(d[3]) : "r"(addr));
}

__device__ __forceinline__ void mma_f16(float* c, const uint32_t* a, const uint32_t* b) {
    asm volatile(
        "mma.sync.aligned.m16n8k16.row.col.f32.f16.f16.f32 "
        "{%0,%1,%2,%3}, {%4,%5,%6,%7}, {%8,%9}, {%0,%1,%2,%3};"
        : "+f"(c[0]), "+f"(c[1]), "+f"(c[2]), "+f"(c[3])
        : "r"(a[0]), "r"(a[1]), "r"(a[2]), "r"(a[3]), "r"(b[0]), "r"(b[1]));
}

// ---- pass 1: f32 -> f16 ----
__global__ void __launch_bounds__(256)
cvt_f32_to_f16(const float* __restrict__ A, const float* __restrict__ B)
{
    const size_t i = ((size_t)blockIdx.x * 256 + threadIdx.x) * 8;
    const float* src = blockIdx.y ? B : A;
    __half* dst = blockIdx.y ? g_Bh : g_Ah;
    float4 v0 = *(const float4*)(src + i);
    float4 v1 = *(const float4*)(src + i + 4);
    __half2 h0 = __floats2half2_rn(v0.x, v0.y);
    __half2 h1 = __floats2half2_rn(v0.z, v0.w);
    __half2 h2 = __floats2half2_rn(v1.x, v1.y);
    __half2 h3 = __floats2half2_rn(v1.z, v1.w);
    uint4 o;
    o.x = *(uint32_t*)&h0; o.y = *(uint32_t*)&h1;
    o.z = *(uint32_t*)&h2; o.w = *(uint32_t*)&h3;
    *(uint4*)(dst + i) = o;
}

// ---- pass 2: GEMM ----
__global__ void __launch_bounds__(NTHREADS, 2)
bgemm_f16_bk64_kernel(float* __restrict__ C)
{
    extern __shared__ char smem[];
    const uint32_t sb = smem_u32(smem);

    const int tid  = threadIdx.x;
    const int wid  = tid >> 5;
    const int lane = tid & 31;

    const uint32_t fullb  = sb + MB_OFF;
    const uint32_t emptyb = sb + MB_OFF + 40;

    // ---- producer constants: 4+4 cp.async per PRODUCE ----
    // unit idx = i*256 + tid (i=0..3); row = (tid>>3)+32i; u = tid&7
    const int prow0 = tid >> 3;      // 0..31
    const int pu    = tid & 7;
    const uint32_t pdst0 = (uint32_t)prow0 * 128
                         + ((uint32_t)(pu ^ (prow0 & 7)) << 4);   // +4096 per i
    const size_t psrc0 = (size_t)prow0 * (DDIM * 2) + (size_t)pu * 16;  // +16384 per i

    // ---- consumer (ldmatrix) constants ----
    const int warp_m = (wid & 1) * 64;
    const int warp_n = (wid >> 1) * 32;
    const int grp = lane >> 3;
    const int rr  = lane & 7;
    // A groups: (m-lo,k-lo)(m-hi,k-lo)(m-lo,k-hi)(m-hi,k-hi)
    const int rowA  = warp_m + ((grp & 1) << 3) + rr;
    const int koffA = grp >> 1;
    const uint32_t mA7   = (uint32_t)(rowA & 7);
    const uint32_t baseA = (uint32_t)rowA * 128;
    // B groups: (n-lo,k-lo)(n-lo,k-hi)(n-hi,k-lo)(n-hi,k-hi)
    const int rowB  = warp_n + ((grp >> 1) << 3) + rr;
    const int koffB = grp & 1;
    const uint32_t mB7   = (uint32_t)(rowB & 7);
    const uint32_t baseB = (uint32_t)rowB * 128;

#define TILE_PTRS(t, pa, pb)                                                   \
    do {                                                                       \
        const int _bz = (t) >> 6;                                              \
        const int _by = ((t) >> 3) & 7;                                        \
        const int _bx = (t) & 7;                                               \
        (pa) = (const char*)g_Ah + ((size_t)(_bz * RDIM + _by * BM)) * (DDIM * 2) + psrc0; \
        (pb) = (const char*)g_Bh + ((size_t)(_bz * RDIM + _bx * BN)) * (DDIM * 2) + psrc0; \
    } while (0)

#define PRODUCE(pa, pb, ko)                                                    \
    do {                                                                       \
        mbar_wait(emptyb + sp * 8, pp);                                        \
        const uint32_t _a = sb + sp * STAGE_BYTES + pdst0;                     \
        const uint32_t _b = sb + B_BASE + sp * STAGE_BYTES + pdst0;            \
        _Pragma("unroll")                                                      \
        for (int _i = 0; _i < 4; _i++) {                                       \
            cp_async16(_a + _i * 4096, (pa) + (ko) + _i * 16384);              \
            cp_async16(_b + _i * 4096, (pb) + (ko) + _i * 16384);              \
        }                                                                      \
        cp_arrive_noinc(fullb + sp * 8);                                       \
        sp = (sp + 1 == STAGES) ? 0 : sp + 1;                                  \
        if (sp == 0) pp ^= 1;                                                  \
    } while (0)

    if (tid == 0) {
        #pragma unroll
        for (int s = 0; s < STAGES; s++) {
            mbar_init(fullb + s * 8, NTHREADS);
            mbar_init(emptyb + s * 8, 8);
        }
    }
    __syncthreads();

    float acc[4][4][4];
    #pragma unroll
    for (int i = 0; i < 4; i++)
        #pragma unroll
        for (int j = 0; j < 4; j++)
            #pragma unroll
            for (int k = 0; k < 4; k++)
                acc[i][j][k] = 0.0f;

    int t = blockIdx.x;
    const char *gAc, *gBc, *gAn, *gBn;
    TILE_PTRS(t, gAc, gBc);

    int sp = 0, pp = 1;
    int sc = 0, pc = 0;

    // prologue: 2 stages in flight (ko byte step = BK*2 = 128)
    PRODUCE(gAc, gBc, 0);
    PRODUCE(gAc, gBc, 128);

    for (; t < NTILES; t += GRIDC) {
        const int tn = t + GRIDC;
        const bool has_next = tn < NTILES;
        if (has_next) TILE_PTRS(tn, gAn, gBn);

        for (int kt = 0; kt < KTILES; kt++) {
            mbar_wait(fullb + sc * 8, pc);
            const uint32_t aS = sb + sc * STAGE_BYTES + baseA;
            const uint32_t bS = sb + B_BASE + sc * STAGE_BYTES + baseB;

            #pragma unroll
            for (int kc = 0; kc < 4; kc++) {      // four k16 chunks per BK=64
                const uint32_t oA = ((uint32_t)((kc * 2 + koffA)) ^ mA7) << 4;
                const uint32_t oB = ((uint32_t)((kc * 2 + koffB)) ^ mB7) << 4;
                uint32_t af[4][4], bf[2][4];
                #pragma unroll
                for (int mt = 0; mt < 4; mt++)
                    ldsm4(af[mt], aS + mt * 2048 + oA);       // 16 rows per mt
                #pragma unroll
                for (int nt2 = 0; nt2 < 2; nt2++)
                    ldsm4(bf[nt2], bS + nt2 * 2048 + oB);     // FIX: 16 rows = 2048B
                #pragma unroll
                for (int mt = 0; mt < 4; mt++)
                    #pragma unroll
                    for (int nt = 0; nt < 4; nt++)
                        mma_f16(acc[mt][nt], af[mt], &bf[nt >> 1][(nt & 1) * 2]);
            }

            if (lane == 0) mbar_arrive(emptyb + sc * 8);
            sc = (sc + 1 == STAGES) ? 0 : sc + 1;
            if (sc == 0) pc ^= 1;

            const int j = kt + 2;
            if (j < KTILES) {
                PRODUCE(gAc, gBc, j * 128);
            } else if (has_next) {
                PRODUCE(gAn, gBn, (j - KTILES) * 128);
            }
        }

        // ---- epilogue ----
        {
            const int bz = t >> 6;
            const int by = (t >> 3) & 7;
            const int bx = t & 7;
            const int g  = lane >> 2;
            const int tg = lane & 3;
            float* Cw = C + (size_t)bz * RDIM * RDIM
                          + (size_t)(by * BM + warp_m) * RDIM + bx * BN + warp_n;
            #pragma unroll
            for (int mt = 0; mt < 4; mt++) {
                #pragma unroll
                for (int nt = 0; nt < 4; nt++) {
                    float* p0 = Cw + (size_t)(mt * 16 + g) * RDIM + nt * 8 + 2 * tg;
                    float* p1 = p0 + 8 * RDIM;
                    *(float2*)p0 = make_float2(acc[mt][nt][0], acc[mt][nt][1]);
                    *(float2*)p1 = make_float2(acc[mt][nt][2], acc[mt][nt][3]);
                    acc[mt][nt][0] = 0.0f; acc[mt][nt][1] = 0.0f;
                    acc[mt][nt][2] = 0.0f; acc[mt][nt][3] = 0.0f;
                }
            }
        }

        gAc = gAn;
        gBc = gBn;
    }
}

extern "C" void kernel_launch(void* const* d_in, const int* in_sizes, int n_in,
                              void* d_out, int out_size)
{
    const float* A = (const float*)d_in[0];  // matrix_1 [16,1024,256]
    const float* B = (const float*)d_in[1];  // matrix_2 [16,1024,256]
    float* C = (float*)d_out;                // [16,1024,1024]

    dim3 cgrid(2048, 2);
    cvt_f32_to_f16<<<cgrid, 256>>>(A, B);

    cudaFuncSetAttribute(bgemm_f16_bk64_kernel,
                         cudaFuncAttributeMaxDynamicSharedMemorySize, SMEM_TOTAL);
    bgemm_f16_bk64_kernel<<<GRIDC, NTHREADS, SMEM_TOTAL>>>(C);
}